// round 10
// baseline (speedup 1.0000x reference)
#include <cuda_runtime.h>

#define FDIM 1024
#define CDIM 64
#define NROWS 65536
#define RPB 8                          // warps (row streams) per block
#define NTHREADS (RPB * 32)
#define NBLOCKS (148 * 3)              // persistent: 3 blocks/SM
#define NWARPS_TOTAL (NBLOCKS * RPB)
#define PADF 1216                      // padded sorted row length (1024 + 64*3)

#define NEG_INF __int_as_float(0xff800000)

// Scratch (no allocations allowed)
__device__ double g_acc[64];           // interleaved loss accumulators (zero-init)
__device__ int    g_done;              // finished-block counter (zero-init)

__global__ void __launch_bounds__(NTHREADS, 3) mix_kernel(
    const float* __restrict__ logits,
    const int*   __restrict__ labels,
    const float* __restrict__ mask,
    float*       __restrict__ out)
{
    __shared__ float          sslice[RPB][PADF];  // 38 KB padded sorted rows
    __shared__ unsigned short smeta16[FDIM];      // 2 KB: sorted position per f
    __shared__ int            spstart[CDIM + 1];
    __shared__ int            scnt[CDIM];
    __shared__ int            s_w0sum;

    const int t    = threadIdx.x;
    const int lane = t & 31;
    const int w    = t >> 5;

    // ---- Block-local setup (redundant per block; mask is L2-resident) ----
    if (t < CDIM) scnt[t] = 0;
    __syncthreads();

    int segs[4], ranks[4];
#pragma unroll
    for (int i = 0; i < 4; i++) {
        int f = t + 256 * i;
        const float4* mrow = reinterpret_cast<const float4*>(mask + f * CDIM);
        float acc = 0.0f;
#pragma unroll
        for (int q = 0; q < 16; q++) {
            float4 m = mrow[q];
            float c0 = (float)(4 * q);
            acc = fmaf(m.x, c0,        acc);
            acc = fmaf(m.y, c0 + 1.0f, acc);
            acc = fmaf(m.z, c0 + 2.0f, acc);
            acc = fmaf(m.w, c0 + 3.0f, acc);
        }
        segs[i]  = (int)(acc + 0.5f);                 // one-hot argmax
        ranks[i] = atomicAdd(&scnt[segs[i]], 1);      // order irrelevant
    }
    __syncthreads();

    // exclusive prefix of 4-padded group counts (threads 0..63)
    int v = 0, sc = 0;
    if (t < CDIM) {
        v = (scnt[t] + 3) & ~3;
        sc = v;
#pragma unroll
        for (int o = 1; o < 32; o <<= 1) {
            int n = __shfl_up_sync(0xFFFFFFFFu, sc, o);
            if (lane >= o) sc += n;
        }
        if (t == 31) s_w0sum = sc;
    }
    __syncthreads();
    if (t < CDIM) {
        int base = sc - v + ((t >= 32) ? s_w0sum : 0);
        spstart[t] = base;
        if (t == 63) spstart[64] = base + v;
    }
    __syncthreads();
#pragma unroll
    for (int i = 0; i < 4; i++) {
        int f = t + 256 * i;
        smeta16[f] = (unsigned short)(spstart[segs[i]] + ranks[i]);
    }
    __syncthreads();

    // ---- Per-warp prologue: positions into registers, slice init ----
    const uint2* mp = reinterpret_cast<const uint2*>(smeta16);  // 4 positions each
    uint2 m0 = mp[lane];        uint2 m1 = mp[lane + 32];
    uint2 m2 = mp[lane + 64];   uint2 m3 = mp[lane + 96];
    uint2 m4 = mp[lane + 128];  uint2 m5 = mp[lane + 160];
    uint2 m6 = mp[lane + 192];  uint2 m7 = mp[lane + 224];

    float*  my  = sslice[w];
    float4* my4 = reinterpret_cast<float4*>(my);
    for (int i = lane; i < PADF / 4; i += 32)      // pads stay -inf forever
        my4[i] = make_float4(NEG_INF, NEG_INF, NEG_INF, NEG_INF);
    __syncwarp();

    const int a0 = spstart[lane],      b0 = spstart[lane + 1];
    const int a1 = spstart[lane + 32], b1 = spstart[lane + 33];

    // ---- Row loop ----
    for (int row = blockIdx.x * RPB + w; row < NROWS; row += NWARPS_TOTAL) {
        const int label  = __ldg(&labels[row]);
        const unsigned lstart = (unsigned)spstart[label];
        const unsigned llen   = (unsigned)(spstart[label + 1]) - lstart;

        const float4* rp = reinterpret_cast<const float4*>(logits + (size_t)row * FDIM);
        float4 v0 = rp[lane];
        float4 v1 = rp[lane + 32];
        float4 v2 = rp[lane + 64];
        float4 v3 = rp[lane + 96];
        float4 v4 = rp[lane + 128];
        float4 v5 = rp[lane + 160];
        float4 v6 = rp[lane + 192];
        float4 v7 = rp[lane + 224];

        float tot = 0.0f, ls = 0.0f;

        // element in label group  <=>  pos in [lstart, lstart+llen)
#define DO_CHUNK(VV, MM)                                                     \
        {                                                                    \
            unsigned p0 = MM.x & 0xFFFFu, p1 = MM.x >> 16;                   \
            unsigned p2 = MM.y & 0xFFFFu, p3 = MM.y >> 16;                   \
            { float e = __expf(VV.x); tot += e;                              \
              if (p0 - lstart < llen) ls += e;  my[p0] = VV.x; }             \
            { float e = __expf(VV.y); tot += e;                              \
              if (p1 - lstart < llen) ls += e;  my[p1] = VV.y; }             \
            { float e = __expf(VV.z); tot += e;                              \
              if (p2 - lstart < llen) ls += e;  my[p2] = VV.z; }             \
            { float e = __expf(VV.w); tot += e;                              \
              if (p3 - lstart < llen) ls += e;  my[p3] = VV.w; }             \
        }
        DO_CHUNK(v0, m0) DO_CHUNK(v1, m1) DO_CHUNK(v2, m2) DO_CHUNK(v3, m3)
        DO_CHUNK(v4, m4) DO_CHUNK(v5, m5) DO_CHUNK(v6, m6) DO_CHUNK(v7, m7)
#undef DO_CHUNK

        __syncwarp();   // scatter -> scan

        // aligned maskless segment max: lane handles groups lane, lane+32
        float gm0 = NEG_INF, gm1 = NEG_INF;
        for (int q = a0 >> 2; q < (b0 >> 2); q++) {
            float4 c = my4[q];
            gm0 = fmaxf(gm0, fmaxf(fmaxf(c.x, c.y), fmaxf(c.z, c.w)));
        }
        for (int q = a1 >> 2; q < (b1 >> 2); q++) {
            float4 c = my4[q];
            gm1 = fmaxf(gm1, fmaxf(fmaxf(c.x, c.y), fmaxf(c.z, c.w)));
        }
        __syncwarp();   // scan done before next row's scatter

        float cand = (label < 32) ? gm0 : gm1;
        float gml  = __shfl_sync(0xFFFFFFFFu, cand, label & 31);

        float csum = __expf(gm0) + __expf(gm1);
#pragma unroll
        for (int o = 16; o; o >>= 1) {
            csum += __shfl_xor_sync(0xFFFFFFFFu, csum, o);
            tot  += __shfl_xor_sync(0xFFFFFFFFu, tot, o);
            ls   += __shfl_xor_sync(0xFFFFFFFFu, ls, o);
        }

        if (lane == 0) {
            float ce  = logf(csum) - gml;        // lse(coarse_max) - gmax[label]
            float nll = logf(tot) - logf(ls);    // log(total) - log(group_sum)
            atomicAdd(&g_acc[row & 63], (double)(0.5f * (ce + nll)));
        }
    }

    // ---- Fused finalize: last block sums, writes, resets for replay ----
    __syncthreads();
    if (t == 0) {
        __threadfence();
        if (atomicAdd(&g_done, 1) == NBLOCKS - 1) {
            __threadfence();
            double s = 0.0;
#pragma unroll
            for (int i = 0; i < 64; i++) s += g_acc[i];
            out[0] = (float)(s / (double)NROWS);
#pragma unroll
            for (int i = 0; i < 64; i++) g_acc[i] = 0.0;   // reset for next replay
            __threadfence();
            g_done = 0;
        }
    }
}

extern "C" void kernel_launch(void* const* d_in, const int* in_sizes, int n_in,
                              void* d_out, int out_size) {
    const float* logits = (const float*)d_in[0];  // [32, 2048, 1024] f32
    const int*   labels = (const int*)d_in[1];    // [32, 2048] i32
    const float* mask   = (const float*)d_in[2];  // [1024, 64] f32

    mix_kernel<<<NBLOCKS, NTHREADS>>>(logits, labels, mask, (float*)d_out);
}

// round 11
// speedup vs baseline: 1.0012x; 1.0012x over previous
#include <cuda_runtime.h>

#define FDIM 1024
#define CDIM 64
#define NROWS 65536
#define NPAIRS (NROWS / 2)
#define RPB 4                          // warps (row-pair streams) per block
#define NTHREADS (RPB * 32)
#define NBLOCKS (148 * 5)              // 5 blocks/SM (41KB smem each)
#define NWARPS_TOTAL (NBLOCKS * RPB)
#define PADF 1216                      // padded sorted positions (1024 + 64*3)

#define NEG_INF __int_as_float(0xff800000)

// Scratch (no allocations allowed)
__device__ unsigned short g_meta16[FDIM];    // sorted position per fine index
__device__ int            g_pstart[CDIM + 1];
__device__ double         g_acc[64];         // interleaved loss accumulators

// ---------------------------------------------------------------------------
// Setup <<<1, 256>>>: seg via one-hot dot product, ranks via smem atomics,
// 4-padded prefix scan, 16-bit positions. Also zeroes accumulators.
// ---------------------------------------------------------------------------
__global__ void setup_kernel(const float* __restrict__ mask) {
    __shared__ int scnt[CDIM];
    __shared__ int sbase[CDIM];
    __shared__ int s_w0sum;
    const int t = threadIdx.x;
    const int lane = t & 31;

    if (t < CDIM) scnt[t] = 0;
    __syncthreads();

    int segs[4], ranks[4];
#pragma unroll
    for (int i = 0; i < 4; i++) {
        int f = t + 256 * i;
        const float4* mrow = reinterpret_cast<const float4*>(mask + f * CDIM);
        float acc = 0.0f;
#pragma unroll
        for (int q = 0; q < 16; q++) {
            float4 m = mrow[q];
            float c0 = (float)(4 * q);
            acc = fmaf(m.x, c0,        acc);
            acc = fmaf(m.y, c0 + 1.0f, acc);
            acc = fmaf(m.z, c0 + 2.0f, acc);
            acc = fmaf(m.w, c0 + 3.0f, acc);
        }
        segs[i]  = (int)(acc + 0.5f);
        ranks[i] = atomicAdd(&scnt[segs[i]], 1);
    }
    __syncthreads();

    int v = 0, sc = 0;
    if (t < CDIM) {
        v = (scnt[t] + 3) & ~3;                  // pad groups to multiple of 4
        sc = v;
#pragma unroll
        for (int o = 1; o < 32; o <<= 1) {
            int n = __shfl_up_sync(0xFFFFFFFFu, sc, o);
            if (lane >= o) sc += n;
        }
        if (t == 31) s_w0sum = sc;
    }
    __syncthreads();
    if (t < CDIM) {
        int base = sc - v + ((t >= 32) ? s_w0sum : 0);
        sbase[t] = base;
        g_pstart[t] = base;
        if (t == 63) g_pstart[64] = base + v;
        g_acc[t] = 0.0;                          // re-zero each launch/replay
    }
    __syncthreads();

#pragma unroll
    for (int i = 0; i < 4; i++) {
        int f = t + 256 * i;
        g_meta16[f] = (unsigned short)(sbase[segs[i]] + ranks[i]);
    }
}

// ---------------------------------------------------------------------------
// Main: persistent warp-per-ROW-PAIR. Same column of rows 2p,2p+1 loaded by
// the same thread; one STS.64 scatters both rows; scan LDS.128 covers
// 2 positions x 2 rows. Halves scatter/meta/epilogue wavefronts per row.
// ---------------------------------------------------------------------------
__global__ void __launch_bounds__(NTHREADS, 5) mix_kernel(
    const float* __restrict__ logits,
    const int*   __restrict__ labels)
{
    __shared__ float2         sslice[RPB][PADF];   // 38.9 KB {rowA,rowB} sorted
    __shared__ unsigned short smeta16[FDIM];       // 2 KB positions
    __shared__ int            spstart[CDIM + 1];

    const int t    = threadIdx.x;
    const int lane = t & 31;
    const int w    = t >> 5;

    // block prologue
    reinterpret_cast<uint4*>(smeta16)[t] = reinterpret_cast<const uint4*>(g_meta16)[t];
    if (t <= CDIM) spstart[t] = g_pstart[t];
    __syncthreads();

    float2* my2 = sslice[w];
    float4* my4 = reinterpret_cast<float4*>(my2);
    for (int i = lane; i < PADF / 2; i += 32)      // pads stay -inf forever
        my4[i] = make_float4(NEG_INF, NEG_INF, NEG_INF, NEG_INF);
    __syncwarp();

    const int qa0 = spstart[lane]      >> 1, qb0 = spstart[lane + 1]  >> 1;
    const int qa1 = spstart[lane + 32] >> 1, qb1 = spstart[lane + 33] >> 1;

    const ushort4* mp = reinterpret_cast<const ushort4*>(smeta16);

    for (int pi = blockIdx.x * RPB + w; pi < NPAIRS; pi += NWARPS_TOTAL) {
        const int2 lab = __ldg(&reinterpret_cast<const int2*>(labels)[pi]);
        const unsigned lsA = (unsigned)spstart[lab.x];
        const unsigned llA = (unsigned)spstart[lab.x + 1] - lsA;
        const unsigned lsB = (unsigned)spstart[lab.y];
        const unsigned llB = (unsigned)spstart[lab.y + 1] - lsB;

        // 16 independent coalesced LDG.128 (rows 2pi, 2pi+1, same columns)
        const float4* rA = reinterpret_cast<const float4*>(logits + (size_t)(2 * pi) * FDIM);
        const float4* rB = rA + (FDIM / 4);
        float4 va[8], vb[8];
#pragma unroll
        for (int c = 0; c < 8; c++) { va[c] = rA[lane + 32 * c]; }
#pragma unroll
        for (int c = 0; c < 8; c++) { vb[c] = rB[lane + 32 * c]; }

        float totA = 0.f, sumA = 0.f, totB = 0.f, sumB = 0.f;

#define PROC(XA, XB, P)                                                      \
        {                                                                    \
            unsigned p = (unsigned)(P);                                      \
            float eA = __expf(XA); totA += eA;                               \
            if (p - lsA < llA) sumA += eA;                                   \
            float eB = __expf(XB); totB += eB;                               \
            if (p - lsB < llB) sumB += eB;                                   \
            my2[p] = make_float2(XA, XB);                                    \
        }
#pragma unroll
        for (int c = 0; c < 8; c++) {
            ushort4 m = mp[lane + 32 * c];
            PROC(va[c].x, vb[c].x, m.x)
            PROC(va[c].y, vb[c].y, m.y)
            PROC(va[c].z, vb[c].z, m.z)
            PROC(va[c].w, vb[c].w, m.w)
        }
#undef PROC

        __syncwarp();   // scatter -> scan

        // segment max for both rows: lane owns groups lane and lane+32
        float gA0 = NEG_INF, gB0 = NEG_INF, gA1 = NEG_INF, gB1 = NEG_INF;
        for (int q = qa0; q < qb0; q++) {
            float4 c = my4[q];                       // {A0,B0,A1,B1}
            gA0 = fmaxf(gA0, fmaxf(c.x, c.z));
            gB0 = fmaxf(gB0, fmaxf(c.y, c.w));
        }
        for (int q = qa1; q < qb1; q++) {
            float4 c = my4[q];
            gA1 = fmaxf(gA1, fmaxf(c.x, c.z));
            gB1 = fmaxf(gB1, fmaxf(c.y, c.w));
        }
        __syncwarp();   // scan done before next pair's scatter

        float candA = (lab.x < 32) ? gA0 : gA1;
        float candB = (lab.y < 32) ? gB0 : gB1;
        float gmlA = __shfl_sync(0xFFFFFFFFu, candA, lab.x & 31);
        float gmlB = __shfl_sync(0xFFFFFFFFu, candB, lab.y & 31);

        float csA = __expf(gA0) + __expf(gA1);
        float csB = __expf(gB0) + __expf(gB1);
#pragma unroll
        for (int o = 16; o; o >>= 1) {
            csA  += __shfl_xor_sync(0xFFFFFFFFu, csA, o);
            csB  += __shfl_xor_sync(0xFFFFFFFFu, csB, o);
            totA += __shfl_xor_sync(0xFFFFFFFFu, totA, o);
            totB += __shfl_xor_sync(0xFFFFFFFFu, totB, o);
            sumA += __shfl_xor_sync(0xFFFFFFFFu, sumA, o);
            sumB += __shfl_xor_sync(0xFFFFFFFFu, sumB, o);
        }

        if (lane == 0) {
            float lossA = 0.5f * ((logf(csA) - gmlA) + (logf(totA) - logf(sumA)));
            float lossB = 0.5f * ((logf(csB) - gmlB) + (logf(totB) - logf(sumB)));
            atomicAdd(&g_acc[pi & 63], (double)lossA + (double)lossB);
        }
    }
}

// ---------------------------------------------------------------------------
// Finalize: mean over rows -> d_out[0]
// ---------------------------------------------------------------------------
__global__ void finalize_kernel(float* __restrict__ out) {
    double s = 0.0;
#pragma unroll
    for (int i = 0; i < 64; i++) s += g_acc[i];
    out[0] = (float)(s / (double)NROWS);
}

extern "C" void kernel_launch(void* const* d_in, const int* in_sizes, int n_in,
                              void* d_out, int out_size) {
    const float* logits = (const float*)d_in[0];  // [32, 2048, 1024] f32
    const int*   labels = (const int*)d_in[1];    // [32, 2048] i32
    const float* mask   = (const float*)d_in[2];  // [1024, 64] f32

    setup_kernel<<<1, 256>>>(mask);
    mix_kernel<<<NBLOCKS, NTHREADS>>>(logits, labels);
    finalize_kernel<<<1, 1>>>((float*)d_out);
}